// round 13
// baseline (speedup 1.0000x reference)
#include <cuda_runtime.h>
#include <cuda_fp16.h>
#include <cstdint>

#define HIDDEN 128
#define MAX_NODES 50000
#define MAX_EDGES 500000
#define SCAN_CHUNK 256
#define MAX_SBLOCKS ((MAX_NODES + SCAN_CHUNK - 1) / SCAN_CHUNK)   // 196

// Scratch (static __device__ arrays — zero-initialized at load; no allocation).
__device__ uint2 g_feah[MAX_NODES * 32];           // fea as fp16 (4 halfs / uint2)
__device__ uint2 g_learn1h[MAX_NODES * 32];        // learn1 as fp16
__device__ int   g_counts[MAX_NODES];              // INVARIANT: zero at call entry
__device__ int   g_offsets[MAX_NODES + 1];         // padded-CSR offsets (mult of 4)
__device__ int   g_rank[MAX_EDGES];
__device__ unsigned int g_state[MAX_SBLOCKS];      // lookback state; INVARIANT: zero at entry
// packed edges: low 16 bits = col (n_nodes < 65536), high 16 = fp16 val bits.
// pad word 0u = (col 0, val 0.0) -> contributes nothing.
__device__ __align__(16) unsigned int g_edges[MAX_EDGES + 3 * MAX_NODES];

// ---------------------------------------------------------------------------
// helpers
// ---------------------------------------------------------------------------
__device__ __forceinline__ uint2 pack4h(float4 a) {
    __half2 h01 = __floats2half2_rn(a.x, a.y);
    __half2 h23 = __floats2half2_rn(a.z, a.w);
    uint2 g;
    g.x = *reinterpret_cast<uint32_t*>(&h01);
    g.y = *reinterpret_cast<uint32_t*>(&h23);
    return g;
}

__device__ __forceinline__ float4 unpack4h(uint2 g) {
    __half2 h01 = *reinterpret_cast<__half2*>(&g.x);
    __half2 h23 = *reinterpret_cast<__half2*>(&g.y);
    float2 f01 = __half22float2(h01);
    float2 f23 = __half22float2(h23);
    return make_float4(f01.x, f01.y, f23.x, f23.y);
}

__device__ __forceinline__ void fma4h(float4& acc, float v, uint2 g) {
    float4 f = unpack4h(g);
    acc.x += v * f.x; acc.y += v * f.y; acc.z += v * f.z; acc.w += v * f.w;
}

__device__ __forceinline__ float edge_val(unsigned int e) {
    return __half2float(__ushort_as_half((unsigned short)(e >> 16)));
}
__device__ __forceinline__ unsigned int edge_col(unsigned int e) {
    return e & 0xFFFFu;
}

// ---------------------------------------------------------------------------
// 1) fused: fea->fp16 convert + histogram/rank (counts pre-zeroed invariant)
// ---------------------------------------------------------------------------
__global__ void convert_hist_kernel(const float4* __restrict__ fea,
                                    uint2* __restrict__ feah,
                                    const int* __restrict__ row,
                                    int* __restrict__ counts,
                                    int* __restrict__ rank,
                                    int n_edges, int total4) {
    int i = blockIdx.x * blockDim.x + threadIdx.x;
    if (i < total4) feah[i] = pack4h(__ldg(fea + i));
    if (i < n_edges) rank[i] = atomicAdd(&counts[__ldg(row + i)], 1);
}

// ---------------------------------------------------------------------------
// 2) single-pass decoupled-lookback scan of PADDED counts -> offsets.
//    State word is UNSIGNED: flag = word >> 30 (logical shift!),
//    value = word & 0x3FFFFFFF (padded total <= 650k << 2^30).
//    flag: 0 = invalid, 1 = aggregate available, 2 = inclusive prefix.
//    Single-word flag+value => no memory fence needed.
//    Also writes zero-pad edges for each row's tail slots.
// ---------------------------------------------------------------------------
__global__ void __launch_bounds__(SCAN_CHUNK)
scan_fused_kernel(const int* __restrict__ counts,
                  int* __restrict__ offsets,
                  unsigned int* __restrict__ edges,
                  unsigned int* __restrict__ state,
                  int n, int nblocks) {
    const int t = threadIdx.x;
    const int b = blockIdx.x;
    const int lane = t & 31;
    const int wid = t >> 5;

    int i = b * SCAN_CHUNK + t;
    int c  = (i < n) ? __ldg(counts + i) : 0;
    int cp = (c + 3) & ~3;                 // padded count (multiple of 4)

    // warp-shuffle inclusive scan of cp
    int v = cp;
    #pragma unroll
    for (int off = 1; off < 32; off <<= 1) {
        int u = __shfl_up_sync(0xFFFFFFFFu, v, off);
        if (lane >= off) v += u;
    }
    __shared__ int wsum[8];
    __shared__ int s_bpref;
    if (lane == 31) wsum[wid] = v;
    __syncthreads();
    if (t < 8) {
        int w = wsum[t];
        #pragma unroll
        for (int off = 1; off < 8; off <<= 1) {
            int u = __shfl_up_sync(0xFFu, w, off);
            if (t >= off) w += u;
        }
        wsum[t] = w;
    }
    __syncthreads();
    int block_total = wsum[7];
    int excl_in_block = v - cp + ((wid > 0) ? wsum[wid - 1] : 0);

    // thread 0: publish aggregate, look back, publish inclusive prefix
    if (t == 0) {
        atomicExch(&state[b], (1u << 30) | (unsigned int)block_total);
        unsigned int pref = 0;
        for (int j = b - 1; j >= 0; j--) {
            unsigned int sj;
            do { sj = atomicAdd(&state[j], 0u); } while ((sj >> 30) == 0u);
            pref += sj & 0x3FFFFFFFu;
            if ((sj >> 30) == 2u) break;   // inclusive prefix found: stop
        }
        atomicExch(&state[b], (2u << 30) | (pref + (unsigned int)block_total));
        s_bpref = (int)pref;
        if (b == nblocks - 1) offsets[n] = (int)pref + block_total;
    }
    __syncthreads();

    int run = s_bpref + excl_in_block;      // exclusive offset (multiple of 4)
    if (i < n) {
        offsets[i] = run;
        for (int j = c; j < cp; j++) edges[run + j] = 0u;    // pad edges
    }
}

// ---------------------------------------------------------------------------
// 3) permute edges — no atomics, 1 edge/thread, packed (col:u16 | val:fp16).
//    Also resets the lookback state to zero (invariant for next call).
// ---------------------------------------------------------------------------
__global__ void permute_kernel(const int* __restrict__ row,
                               const int* __restrict__ col,
                               const float* __restrict__ val,
                               const int* __restrict__ rank,
                               const int* __restrict__ offsets,
                               unsigned int* __restrict__ edges,
                               unsigned int* __restrict__ state,
                               int n_edges, int nblocks) {
    int e = blockIdx.x * blockDim.x + threadIdx.x;
    if (e < nblocks) state[e] = 0u;          // restore scan-state invariant
    if (e >= n_edges) return;
    int r = __ldg(row + e);
    int pos = __ldg(offsets + r) + __ldg(rank + e);
    unsigned int c = (unsigned int)__ldg(col + e);
    unsigned short hv = __half_as_ushort(__float2half_rn(__ldg(val + e)));
    edges[pos] = c | ((unsigned int)hv << 16);
}

// ---------------------------------------------------------------------------
// 4) layer 1: learn1h = fp16( spmm_h(fea_h) + bias0 );
//    warp/row; uint4 edge descs (4 edges/LDG); fp16 gathers; fp32 accumulate.
//    Also restores counts==0 invariant for the next call.
// ---------------------------------------------------------------------------
__global__ void __launch_bounds__(256)
spmm1_kernel(const uint2* __restrict__ xh,
             uint2* __restrict__ yh,
             const int* __restrict__ offsets,
             const uint4* __restrict__ edges4,
             const float4* __restrict__ bias4,
             int* __restrict__ counts,
             int n_nodes) {
    int gtid = blockIdx.x * blockDim.x + threadIdx.x;
    if (gtid < n_nodes) counts[gtid] = 0;      // restore invariant
    int r = gtid >> 5;
    if (r >= n_nodes) return;
    int lane = threadIdx.x & 31;

    float4 acc = __ldg(bias4 + lane);
    int beg = __ldg(offsets + r);        // multiple of 4
    int end = __ldg(offsets + r + 1);    // multiple of 4

    int i = beg;
    for (; i + 8 <= end; i += 8) {
        uint4 d0 = __ldg(edges4 + (i >> 2));
        uint4 d1 = __ldg(edges4 + (i >> 2) + 1);
        uint2 g0 = __ldg(xh + (size_t)edge_col(d0.x) * 32 + lane);
        uint2 g1 = __ldg(xh + (size_t)edge_col(d0.y) * 32 + lane);
        uint2 g2 = __ldg(xh + (size_t)edge_col(d0.z) * 32 + lane);
        uint2 g3 = __ldg(xh + (size_t)edge_col(d0.w) * 32 + lane);
        uint2 g4 = __ldg(xh + (size_t)edge_col(d1.x) * 32 + lane);
        uint2 g5 = __ldg(xh + (size_t)edge_col(d1.y) * 32 + lane);
        uint2 g6 = __ldg(xh + (size_t)edge_col(d1.z) * 32 + lane);
        uint2 g7 = __ldg(xh + (size_t)edge_col(d1.w) * 32 + lane);
        fma4h(acc, edge_val(d0.x), g0);
        fma4h(acc, edge_val(d0.y), g1);
        fma4h(acc, edge_val(d0.z), g2);
        fma4h(acc, edge_val(d0.w), g3);
        fma4h(acc, edge_val(d1.x), g4);
        fma4h(acc, edge_val(d1.y), g5);
        fma4h(acc, edge_val(d1.z), g6);
        fma4h(acc, edge_val(d1.w), g7);
    }
    if (i < end) {                        // tail of exactly 4 edges
        uint4 d0 = __ldg(edges4 + (i >> 2));
        uint2 g0 = __ldg(xh + (size_t)edge_col(d0.x) * 32 + lane);
        uint2 g1 = __ldg(xh + (size_t)edge_col(d0.y) * 32 + lane);
        uint2 g2 = __ldg(xh + (size_t)edge_col(d0.z) * 32 + lane);
        uint2 g3 = __ldg(xh + (size_t)edge_col(d0.w) * 32 + lane);
        fma4h(acc, edge_val(d0.x), g0);
        fma4h(acc, edge_val(d0.y), g1);
        fma4h(acc, edge_val(d0.z), g2);
        fma4h(acc, edge_val(d0.w), g3);
    }

    yh[(size_t)r * 32 + lane] = pack4h(acc);
}

// ---------------------------------------------------------------------------
// 5) layer 2 + fused final: out = (feah + learn1h + spmm_h(learn1h)+bias1)/3
// ---------------------------------------------------------------------------
__global__ void __launch_bounds__(256)
spmm2_kernel(const uint2* __restrict__ xh,       // learn1 fp16
             const uint2* __restrict__ feah,     // fea fp16
             float4* __restrict__ out,
             const int* __restrict__ offsets,
             const uint4* __restrict__ edges4,
             const float4* __restrict__ bias4,
             int n_nodes) {
    int gtid = blockIdx.x * blockDim.x + threadIdx.x;
    int r = gtid >> 5;
    if (r >= n_nodes) return;
    int lane = threadIdx.x & 31;

    float4 acc = __ldg(bias4 + lane);
    int beg = __ldg(offsets + r);
    int end = __ldg(offsets + r + 1);

    int i = beg;
    for (; i + 8 <= end; i += 8) {
        uint4 d0 = __ldg(edges4 + (i >> 2));
        uint4 d1 = __ldg(edges4 + (i >> 2) + 1);
        uint2 g0 = __ldg(xh + (size_t)edge_col(d0.x) * 32 + lane);
        uint2 g1 = __ldg(xh + (size_t)edge_col(d0.y) * 32 + lane);
        uint2 g2 = __ldg(xh + (size_t)edge_col(d0.z) * 32 + lane);
        uint2 g3 = __ldg(xh + (size_t)edge_col(d0.w) * 32 + lane);
        uint2 g4 = __ldg(xh + (size_t)edge_col(d1.x) * 32 + lane);
        uint2 g5 = __ldg(xh + (size_t)edge_col(d1.y) * 32 + lane);
        uint2 g6 = __ldg(xh + (size_t)edge_col(d1.z) * 32 + lane);
        uint2 g7 = __ldg(xh + (size_t)edge_col(d1.w) * 32 + lane);
        fma4h(acc, edge_val(d0.x), g0);
        fma4h(acc, edge_val(d0.y), g1);
        fma4h(acc, edge_val(d0.z), g2);
        fma4h(acc, edge_val(d0.w), g3);
        fma4h(acc, edge_val(d1.x), g4);
        fma4h(acc, edge_val(d1.y), g5);
        fma4h(acc, edge_val(d1.z), g6);
        fma4h(acc, edge_val(d1.w), g7);
    }
    if (i < end) {                        // tail of exactly 4 edges
        uint4 d0 = __ldg(edges4 + (i >> 2));
        uint2 g0 = __ldg(xh + (size_t)edge_col(d0.x) * 32 + lane);
        uint2 g1 = __ldg(xh + (size_t)edge_col(d0.y) * 32 + lane);
        uint2 g2 = __ldg(xh + (size_t)edge_col(d0.z) * 32 + lane);
        uint2 g3 = __ldg(xh + (size_t)edge_col(d0.w) * 32 + lane);
        fma4h(acc, edge_val(d0.x), g0);
        fma4h(acc, edge_val(d0.y), g1);
        fma4h(acc, edge_val(d0.z), g2);
        fma4h(acc, edge_val(d0.w), g3);
    }

    size_t idx = (size_t)r * 32 + lane;
    const float inv3 = 1.0f / 3.0f;
    float4 f  = unpack4h(__ldg(feah + idx));   // fp16 residual fea
    float4 l1 = unpack4h(__ldg(xh + idx));     // fp16 residual learn1
    acc.x = (f.x + l1.x + acc.x) * inv3;
    acc.y = (f.y + l1.y + acc.y) * inv3;
    acc.z = (f.z + l1.z + acc.z) * inv3;
    acc.w = (f.w + l1.w + acc.w) * inv3;
    __stcs(out + idx, acc);                    // streaming store
}

extern "C" void kernel_launch(void* const* d_in, const int* in_sizes, int n_in,
                              void* d_out, int out_size) {
    const float* fea     = (const float*)d_in[0];
    const int*   adj_row = (const int*)  d_in[1];
    const int*   adj_col = (const int*)  d_in[2];
    const float* adj_val = (const float*)d_in[3];
    const float* bias    = (const float*)d_in[4];

    int n_edges = in_sizes[1];
    int n_nodes = in_sizes[0] / HIDDEN;
    int total4  = n_nodes * 32;
    int nblocks_scan = (n_nodes + SCAN_CHUNK - 1) / SCAN_CHUNK;   // 196

    uint2* feah;    cudaGetSymbolAddress((void**)&feah,    g_feah);
    uint2* learn1h; cudaGetSymbolAddress((void**)&learn1h, g_learn1h);
    int*   counts;  cudaGetSymbolAddress((void**)&counts,  g_counts);
    int*   offs;    cudaGetSymbolAddress((void**)&offs,    g_offsets);
    int*   rank;    cudaGetSymbolAddress((void**)&rank,    g_rank);
    unsigned int* state; cudaGetSymbolAddress((void**)&state, g_state);
    unsigned int* edges; cudaGetSymbolAddress((void**)&edges, g_edges);
    float* out = (float*)d_out;

    const int TPB = 256;

    // 1) fused fp16 convert + histogram/rank
    {
        int work = max(total4, n_edges);
        convert_hist_kernel<<<(work + TPB - 1) / TPB, TPB>>>(
            (const float4*)fea, feah, adj_row, counts, rank, n_edges, total4);
    }

    // 2) single-pass decoupled-lookback scan -> offsets (+ pad edges)
    scan_fused_kernel<<<nblocks_scan, SCAN_CHUNK>>>(counts, offs, edges, state,
                                                    n_nodes, nblocks_scan);

    // 3) permute edges (+ reset scan state)
    permute_kernel<<<(n_edges + TPB - 1) / TPB, TPB>>>(adj_row, adj_col, adj_val,
                                                       rank, offs, edges, state,
                                                       n_edges, nblocks_scan);

    // 4) layer 1 (+ restore counts==0)
    {
        int blocks = (n_nodes * 32 + 255) / 256;
        spmm1_kernel<<<blocks, 256>>>(feah, learn1h, offs, (const uint4*)edges,
                                      (const float4*)bias, counts, n_nodes);
    }

    // 5) layer 2 + fused final
    {
        int blocks = (n_nodes * 32 + 255) / 256;
        spmm2_kernel<<<blocks, 256>>>(learn1h, feah, (float4*)out,
                                      offs, (const uint4*)edges,
                                      (const float4*)(bias + HIDDEN), n_nodes);
    }
}

// round 14
// speedup vs baseline: 1.0654x; 1.0654x over previous
#include <cuda_runtime.h>
#include <cuda_fp16.h>
#include <cstdint>

#define HIDDEN 128
#define MAX_NODES 50000
#define MAX_EDGES 500000
#define SCAN_CHUNK 256
#define MAX_SBLOCKS ((MAX_NODES + SCAN_CHUNK - 1) / SCAN_CHUNK)   // 196

// Scratch (static __device__ arrays — zero-initialized at load; no allocation).
__device__ uint2 g_feah[MAX_NODES * 32];           // fea as fp16 (row = 256B)
__device__ uint2 g_learn1h[MAX_NODES * 32];        // learn1 as fp16
__device__ int   g_counts[MAX_NODES];              // INVARIANT: zero at call entry
__device__ int   g_offsets[MAX_NODES + 1];         // padded-CSR offsets (mult of 4)
__device__ int   g_rank[MAX_EDGES];
__device__ int   g_bsum[MAX_SBLOCKS];
// packed edges: low 16 bits = col (n_nodes < 65536), high 16 = fp16 val bits.
// pad word 0u = (col 0, val 0.0) -> contributes nothing.
__device__ __align__(16) unsigned int g_edges[MAX_EDGES + 3 * MAX_NODES];

// ---------------------------------------------------------------------------
// helpers
// ---------------------------------------------------------------------------
__device__ __forceinline__ uint2 pack4h(float4 a) {
    __half2 h01 = __floats2half2_rn(a.x, a.y);
    __half2 h23 = __floats2half2_rn(a.z, a.w);
    uint2 g;
    g.x = *reinterpret_cast<uint32_t*>(&h01);
    g.y = *reinterpret_cast<uint32_t*>(&h23);
    return g;
}

__device__ __forceinline__ float2 h2f2(unsigned int h) {
    __half2 hh = *reinterpret_cast<__half2*>(&h);
    return __half22float2(hh);
}

__device__ __forceinline__ float edge_val(unsigned int e) {
    return __half2float(__ushort_as_half((unsigned short)(e >> 16)));
}

// accumulate v * (8 fp16 in uint4) into acc[8] (fp32)
__device__ __forceinline__ void fma8(float* acc, float v, uint4 g) {
    float2 f0 = h2f2(g.x), f1 = h2f2(g.y), f2 = h2f2(g.z), f3 = h2f2(g.w);
    acc[0] += v * f0.x; acc[1] += v * f0.y;
    acc[2] += v * f1.x; acc[3] += v * f1.y;
    acc[4] += v * f2.x; acc[5] += v * f2.y;
    acc[6] += v * f3.x; acc[7] += v * f3.y;
}

// ---------------------------------------------------------------------------
// 1) fused: fea->fp16 convert + histogram/rank (counts pre-zeroed invariant)
// ---------------------------------------------------------------------------
__global__ void convert_hist_kernel(const float4* __restrict__ fea,
                                    uint2* __restrict__ feah,
                                    const int* __restrict__ row,
                                    int* __restrict__ counts,
                                    int* __restrict__ rank,
                                    int n_edges, int total4) {
    int i = blockIdx.x * blockDim.x + threadIdx.x;
    if (i < total4) feah[i] = pack4h(__ldg(fea + i));
    if (i < n_edges) rank[i] = atomicAdd(&counts[__ldg(row + i)], 1);
}

// ---------------------------------------------------------------------------
// 2) per-256-chunk block sums of PADDED counts ((c+3)&~3) — 196 blocks
// ---------------------------------------------------------------------------
__global__ void scan_bsum_kernel(const int* __restrict__ counts,
                                 int* __restrict__ bsum, int n) {
    __shared__ int s[SCAN_CHUNK];
    int t = threadIdx.x;
    int i = blockIdx.x * SCAN_CHUNK + t;
    s[t] = (i < n) ? ((__ldg(counts + i) + 3) & ~3) : 0;
    __syncthreads();
    for (int off = 1; off < SCAN_CHUNK; off <<= 1) {
        int v = (t >= off) ? s[t - off] : 0;
        __syncthreads();
        s[t] += v;
        __syncthreads();
    }
    if (t == SCAN_CHUNK - 1) bsum[blockIdx.x] = s[SCAN_CHUNK - 1];
}

// ---------------------------------------------------------------------------
// 3) final scan: parallel smem scan of bsums, then block-local scan of padded
//    counts -> exclusive offsets (multiple of 4); writes zero-pad edges.
// ---------------------------------------------------------------------------
__global__ void scan_offsets_pad_kernel(const int* __restrict__ counts,
                                        const int* __restrict__ bsum,
                                        int* __restrict__ offsets,
                                        unsigned int* __restrict__ edges,
                                        int n, int nblocks) {
    __shared__ int s[SCAN_CHUNK];
    __shared__ int sb[SCAN_CHUNK];
    int t = threadIdx.x;
    int b = blockIdx.x;

    sb[t] = (t < nblocks) ? __ldg(bsum + t) : 0;
    __syncthreads();
    for (int off = 1; off < SCAN_CHUNK; off <<= 1) {
        int v = (t >= off) ? sb[t - off] : 0;
        __syncthreads();
        sb[t] += v;
        __syncthreads();
    }
    int bpref = (b > 0) ? sb[b - 1] : 0;

    int i = b * SCAN_CHUNK + t;
    int c  = (i < n) ? __ldg(counts + i) : 0;
    int cp = (c + 3) & ~3;
    s[t] = cp;
    __syncthreads();
    for (int off = 1; off < SCAN_CHUNK; off <<= 1) {
        int v = (t >= off) ? s[t - off] : 0;
        __syncthreads();
        s[t] += v;
        __syncthreads();
    }

    int run = bpref + ((t > 0) ? s[t - 1] : 0);   // exclusive offset (mult of 4)
    if (i < n) {
        offsets[i] = run;
        for (int j = c; j < cp; j++) edges[run + j] = 0u;   // pad edges
    }
    if (b == 0 && t == 0) offsets[n] = sb[nblocks - 1];
}

// ---------------------------------------------------------------------------
// 4) permute edges — no atomics, 1 edge/thread, packed (col:u16 | val:fp16)
// ---------------------------------------------------------------------------
__global__ void permute_kernel(const int* __restrict__ row,
                               const int* __restrict__ col,
                               const float* __restrict__ val,
                               const int* __restrict__ rank,
                               const int* __restrict__ offsets,
                               unsigned int* __restrict__ edges, int n_edges) {
    int e = blockIdx.x * blockDim.x + threadIdx.x;
    if (e >= n_edges) return;
    int r = __ldg(row + e);
    int pos = __ldg(offsets + r) + __ldg(rank + e);
    unsigned int c = (unsigned int)__ldg(col + e);
    unsigned short hv = __half_as_ushort(__float2half_rn(__ldg(val + e)));
    edges[pos] = c | ((unsigned int)hv << 16);
}

// ---------------------------------------------------------------------------
// 5) layer 1: learn1h = fp16( spmm_h(fea_h) + bias0 )
//    Half-warp edge pairing: one warp per row; lanes 0-15 process edge 2k,
//    lanes 16-31 edge 2k+1. Each lane gathers uint4 (8 halves) of its edge's
//    source row. One gather LDG covers TWO edges. fp32 accumulate; shfl-merge.
//    Also restores counts==0 invariant.
// ---------------------------------------------------------------------------
__global__ void __launch_bounds__(256)
spmm1_kernel(const char* __restrict__ xh,        // fea fp16 base (256B rows)
             uint4* __restrict__ yh,             // learn1h (16 uint4 per row)
             const int* __restrict__ offsets,
             const uint4* __restrict__ edges4,
             const float4* __restrict__ bias4,   // 32 float4
             int* __restrict__ counts,
             int n_nodes) {
    int gtid = blockIdx.x * blockDim.x + threadIdx.x;
    if (gtid < n_nodes) counts[gtid] = 0;        // restore invariant
    int r = gtid >> 5;
    if (r >= n_nodes) return;
    int lane = threadIdx.x & 31;
    int half = lane >> 4;                        // 0 or 1
    int sub  = lane & 15;                        // column group

    const char* xbase = xh + sub * 16;           // this lane's column slice

    float acc[8];
    if (half == 0) {
        float4 b0 = __ldg(bias4 + sub * 2);
        float4 b1 = __ldg(bias4 + sub * 2 + 1);
        acc[0]=b0.x; acc[1]=b0.y; acc[2]=b0.z; acc[3]=b0.w;
        acc[4]=b1.x; acc[5]=b1.y; acc[6]=b1.z; acc[7]=b1.w;
    } else {
        #pragma unroll
        for (int k = 0; k < 8; k++) acc[k] = 0.0f;
    }

    int beg = __ldg(offsets + r);        // multiple of 4
    int end = __ldg(offsets + r + 1);

    int i = beg;
    for (; i + 8 <= end; i += 8) {       // 2 desc loads, 4 pairs
        uint4 d0 = __ldg(edges4 + (i >> 2));
        uint4 d1 = __ldg(edges4 + (i >> 2) + 1);
        unsigned int e0 = half ? d0.y : d0.x;
        unsigned int e1 = half ? d0.w : d0.z;
        unsigned int e2 = half ? d1.y : d1.x;
        unsigned int e3 = half ? d1.w : d1.z;
        uint4 g0 = __ldg((const uint4*)(xbase + ((e0 & 0xFFFFu) << 8)));
        uint4 g1 = __ldg((const uint4*)(xbase + ((e1 & 0xFFFFu) << 8)));
        uint4 g2 = __ldg((const uint4*)(xbase + ((e2 & 0xFFFFu) << 8)));
        uint4 g3 = __ldg((const uint4*)(xbase + ((e3 & 0xFFFFu) << 8)));
        fma8(acc, edge_val(e0), g0);
        fma8(acc, edge_val(e1), g1);
        fma8(acc, edge_val(e2), g2);
        fma8(acc, edge_val(e3), g3);
    }
    if (i < end) {                       // tail of exactly 4 edges (2 pairs)
        uint4 d0 = __ldg(edges4 + (i >> 2));
        unsigned int e0 = half ? d0.y : d0.x;
        unsigned int e1 = half ? d0.w : d0.z;
        uint4 g0 = __ldg((const uint4*)(xbase + ((e0 & 0xFFFFu) << 8)));
        uint4 g1 = __ldg((const uint4*)(xbase + ((e1 & 0xFFFFu) << 8)));
        fma8(acc, edge_val(e0), g0);
        fma8(acc, edge_val(e1), g1);
    }

    // merge the two half-warp accumulators
    #pragma unroll
    for (int k = 0; k < 8; k++)
        acc[k] += __shfl_xor_sync(0xFFFFFFFFu, acc[k], 16);

    if (half == 0) {                     // lanes 0-15 write 16B each = 256B row
        uint4 o;
        __half2 h01 = __floats2half2_rn(acc[0], acc[1]);
        __half2 h23 = __floats2half2_rn(acc[2], acc[3]);
        __half2 h45 = __floats2half2_rn(acc[4], acc[5]);
        __half2 h67 = __floats2half2_rn(acc[6], acc[7]);
        o.x = *reinterpret_cast<uint32_t*>(&h01);
        o.y = *reinterpret_cast<uint32_t*>(&h23);
        o.z = *reinterpret_cast<uint32_t*>(&h45);
        o.w = *reinterpret_cast<uint32_t*>(&h67);
        yh[r * 16 + sub] = o;
    }
}

// ---------------------------------------------------------------------------
// 6) layer 2 + fused final: out = (feah + learn1h + spmm_h(learn1h)+bias1)/3
//    Same half-warp pairing; lanes 0-15 do the residual+final epilogue.
// ---------------------------------------------------------------------------
__global__ void __launch_bounds__(256)
spmm2_kernel(const char* __restrict__ xh,        // learn1h base (256B rows)
             const char* __restrict__ feah,      // fea fp16 base
             float4* __restrict__ out,           // 32 float4 per row
             const int* __restrict__ offsets,
             const uint4* __restrict__ edges4,
             const float4* __restrict__ bias4,
             int n_nodes) {
    int gtid = blockIdx.x * blockDim.x + threadIdx.x;
    int r = gtid >> 5;
    if (r >= n_nodes) return;
    int lane = threadIdx.x & 31;
    int half = lane >> 4;
    int sub  = lane & 15;

    const char* xbase = xh + sub * 16;

    float acc[8];
    if (half == 0) {
        float4 b0 = __ldg(bias4 + sub * 2);
        float4 b1 = __ldg(bias4 + sub * 2 + 1);
        acc[0]=b0.x; acc[1]=b0.y; acc[2]=b0.z; acc[3]=b0.w;
        acc[4]=b1.x; acc[5]=b1.y; acc[6]=b1.z; acc[7]=b1.w;
    } else {
        #pragma unroll
        for (int k = 0; k < 8; k++) acc[k] = 0.0f;
    }

    int beg = __ldg(offsets + r);
    int end = __ldg(offsets + r + 1);

    int i = beg;
    for (; i + 8 <= end; i += 8) {
        uint4 d0 = __ldg(edges4 + (i >> 2));
        uint4 d1 = __ldg(edges4 + (i >> 2) + 1);
        unsigned int e0 = half ? d0.y : d0.x;
        unsigned int e1 = half ? d0.w : d0.z;
        unsigned int e2 = half ? d1.y : d1.x;
        unsigned int e3 = half ? d1.w : d1.z;
        uint4 g0 = __ldg((const uint4*)(xbase + ((e0 & 0xFFFFu) << 8)));
        uint4 g1 = __ldg((const uint4*)(xbase + ((e1 & 0xFFFFu) << 8)));
        uint4 g2 = __ldg((const uint4*)(xbase + ((e2 & 0xFFFFu) << 8)));
        uint4 g3 = __ldg((const uint4*)(xbase + ((e3 & 0xFFFFu) << 8)));
        fma8(acc, edge_val(e0), g0);
        fma8(acc, edge_val(e1), g1);
        fma8(acc, edge_val(e2), g2);
        fma8(acc, edge_val(e3), g3);
    }
    if (i < end) {
        uint4 d0 = __ldg(edges4 + (i >> 2));
        unsigned int e0 = half ? d0.y : d0.x;
        unsigned int e1 = half ? d0.w : d0.z;
        uint4 g0 = __ldg((const uint4*)(xbase + ((e0 & 0xFFFFu) << 8)));
        uint4 g1 = __ldg((const uint4*)(xbase + ((e1 & 0xFFFFu) << 8)));
        fma8(acc, edge_val(e0), g0);
        fma8(acc, edge_val(e1), g1);
    }

    #pragma unroll
    for (int k = 0; k < 8; k++)
        acc[k] += __shfl_xor_sync(0xFFFFFFFFu, acc[k], 16);

    if (half == 0) {
        // residuals (fp16) for this lane's 8 columns
        uint4 fh = __ldg((const uint4*)(feah + r * 256 + sub * 16));
        uint4 lh = __ldg((const uint4*)(xh   + r * 256 + sub * 16));
        float2 f0 = h2f2(fh.x), f1 = h2f2(fh.y), f2 = h2f2(fh.z), f3 = h2f2(fh.w);
        float2 l0 = h2f2(lh.x), l1 = h2f2(lh.y), l2 = h2f2(lh.z), l3 = h2f2(lh.w);
        const float inv3 = 1.0f / 3.0f;
        float4 o0, o1;
        o0.x = (f0.x + l0.x + acc[0]) * inv3;
        o0.y = (f0.y + l0.y + acc[1]) * inv3;
        o0.z = (f1.x + l1.x + acc[2]) * inv3;
        o0.w = (f1.y + l1.y + acc[3]) * inv3;
        o1.x = (f2.x + l2.x + acc[4]) * inv3;
        o1.y = (f2.y + l2.y + acc[5]) * inv3;
        o1.z = (f3.x + l3.x + acc[6]) * inv3;
        o1.w = (f3.y + l3.y + acc[7]) * inv3;
        __stcs(out + r * 32 + sub * 2,     o0);
        __stcs(out + r * 32 + sub * 2 + 1, o1);
    }
}

extern "C" void kernel_launch(void* const* d_in, const int* in_sizes, int n_in,
                              void* d_out, int out_size) {
    const float* fea     = (const float*)d_in[0];
    const int*   adj_row = (const int*)  d_in[1];
    const int*   adj_col = (const int*)  d_in[2];
    const float* adj_val = (const float*)d_in[3];
    const float* bias    = (const float*)d_in[4];

    int n_edges = in_sizes[1];
    int n_nodes = in_sizes[0] / HIDDEN;
    int total4  = n_nodes * 32;
    int nblocks_scan = (n_nodes + SCAN_CHUNK - 1) / SCAN_CHUNK;   // 196

    uint2* feah;    cudaGetSymbolAddress((void**)&feah,    g_feah);
    uint2* learn1h; cudaGetSymbolAddress((void**)&learn1h, g_learn1h);
    int*   counts;  cudaGetSymbolAddress((void**)&counts,  g_counts);
    int*   offs;    cudaGetSymbolAddress((void**)&offs,    g_offsets);
    int*   rank;    cudaGetSymbolAddress((void**)&rank,    g_rank);
    int*   bsum;    cudaGetSymbolAddress((void**)&bsum,    g_bsum);
    unsigned int* edges; cudaGetSymbolAddress((void**)&edges, g_edges);
    float* out = (float*)d_out;

    const int TPB = 256;

    // 1) fused fp16 convert + histogram/rank
    {
        int work = max(total4, n_edges);
        convert_hist_kernel<<<(work + TPB - 1) / TPB, TPB>>>(
            (const float4*)fea, feah, adj_row, counts, rank, n_edges, total4);
    }

    // 2) block sums of padded counts
    scan_bsum_kernel<<<nblocks_scan, SCAN_CHUNK>>>(counts, bsum, n_nodes);

    // 3) offsets scan + pad-edge writes
    scan_offsets_pad_kernel<<<nblocks_scan, SCAN_CHUNK>>>(counts, bsum, offs,
                                                          edges, n_nodes,
                                                          nblocks_scan);

    // 4) permute edges
    permute_kernel<<<(n_edges + TPB - 1) / TPB, TPB>>>(adj_row, adj_col, adj_val,
                                                       rank, offs, edges, n_edges);

    // 5) layer 1 (+ restore counts==0)
    {
        int blocks = (n_nodes * 32 + 255) / 256;
        spmm1_kernel<<<blocks, 256>>>((const char*)feah, (uint4*)learn1h,
                                      offs, (const uint4*)edges,
                                      (const float4*)bias, counts, n_nodes);
    }

    // 6) layer 2 + fused final
    {
        int blocks = (n_nodes * 32 + 255) / 256;
        spmm2_kernel<<<blocks, 256>>>((const char*)learn1h, (const char*)feah,
                                      (float4*)out, offs, (const uint4*)edges,
                                      (const float4*)(bias + HIDDEN), n_nodes);
    }
}

// round 15
// speedup vs baseline: 1.1060x; 1.0381x over previous
#include <cuda_runtime.h>
#include <cuda_fp16.h>
#include <cstdint>

#define HIDDEN 128
#define MAX_NODES 50000
#define MAX_EDGES 500000
#define SCAN_CHUNK 256
#define MAX_SBLOCKS ((MAX_NODES + SCAN_CHUNK - 1) / SCAN_CHUNK)   // 196

// Scratch (static __device__ arrays — zero-initialized at load; no allocation).
__device__ uint2 g_feah[MAX_NODES * 32];           // fea as fp16 (4 halfs / uint2)
__device__ uint2 g_learn1h[MAX_NODES * 32];        // learn1 as fp16
__device__ int   g_counts[MAX_NODES];              // INVARIANT: zero at call entry
__device__ int   g_offsets[MAX_NODES + 1];         // padded-CSR offsets (mult of 4)
__device__ int   g_rank[MAX_EDGES];
__device__ int   g_bsum[MAX_SBLOCKS];
// packed edges: low 16 bits = col (n_nodes < 65536), high 16 = fp16 val bits.
// pad word 0u = (col 0, val 0.0) -> contributes nothing.
__device__ __align__(16) unsigned int g_edges[MAX_EDGES + 3 * MAX_NODES];

// ---------------------------------------------------------------------------
// helpers
// ---------------------------------------------------------------------------
__device__ __forceinline__ uint2 pack4h(float4 a) {
    __half2 h01 = __floats2half2_rn(a.x, a.y);
    __half2 h23 = __floats2half2_rn(a.z, a.w);
    uint2 g;
    g.x = *reinterpret_cast<uint32_t*>(&h01);
    g.y = *reinterpret_cast<uint32_t*>(&h23);
    return g;
}

__device__ __forceinline__ float4 unpack4h(uint2 g) {
    __half2 h01 = *reinterpret_cast<__half2*>(&g.x);
    __half2 h23 = *reinterpret_cast<__half2*>(&g.y);
    float2 f01 = __half22float2(h01);
    float2 f23 = __half22float2(h23);
    return make_float4(f01.x, f01.y, f23.x, f23.y);
}

__device__ __forceinline__ void fma4h(float4& acc, float v, uint2 g) {
    float4 f = unpack4h(g);
    acc.x += v * f.x; acc.y += v * f.y; acc.z += v * f.z; acc.w += v * f.w;
}

__device__ __forceinline__ float edge_val(unsigned int e) {
    return __half2float(__ushort_as_half((unsigned short)(e >> 16)));
}
__device__ __forceinline__ unsigned int edge_col(unsigned int e) {
    return e & 0xFFFFu;
}

// ---------------------------------------------------------------------------
// 1) fused: fea->fp16 convert + histogram/rank (counts pre-zeroed invariant)
// ---------------------------------------------------------------------------
__global__ void convert_hist_kernel(const float4* __restrict__ fea,
                                    uint2* __restrict__ feah,
                                    const int* __restrict__ row,
                                    int* __restrict__ counts,
                                    int* __restrict__ rank,
                                    int n_edges, int total4) {
    int i = blockIdx.x * blockDim.x + threadIdx.x;
    if (i < total4) feah[i] = pack4h(__ldg(fea + i));
    if (i < n_edges) rank[i] = atomicAdd(&counts[__ldg(row + i)], 1);
}

// ---------------------------------------------------------------------------
// 2) per-256-chunk block SUMS of PADDED counts — shfl reduction (fast)
// ---------------------------------------------------------------------------
__global__ void __launch_bounds__(SCAN_CHUNK)
scan_bsum_kernel(const int* __restrict__ counts,
                 int* __restrict__ bsum, int n) {
    __shared__ int wsum[8];
    int t = threadIdx.x;
    int lane = t & 31, wid = t >> 5;
    int i = blockIdx.x * SCAN_CHUNK + t;
    int v = (i < n) ? ((__ldg(counts + i) + 3) & ~3) : 0;
    #pragma unroll
    for (int off = 16; off > 0; off >>= 1)
        v += __shfl_xor_sync(0xFFFFFFFFu, v, off);
    if (lane == 0) wsum[wid] = v;
    __syncthreads();
    if (t == 0) {
        int s = 0;
        #pragma unroll
        for (int k = 0; k < 8; k++) s += wsum[k];
        bsum[blockIdx.x] = s;
    }
}

// ---------------------------------------------------------------------------
// 3) final scan: shfl-based scan of 196 bsums + shfl-based block-local scan
//    of padded counts -> exclusive offsets (multiple of 4); writes pad edges.
// ---------------------------------------------------------------------------
__global__ void __launch_bounds__(SCAN_CHUNK)
scan_offsets_pad_kernel(const int* __restrict__ counts,
                        const int* __restrict__ bsum,
                        int* __restrict__ offsets,
                        unsigned int* __restrict__ edges,
                        int n, int nblocks) {
    __shared__ int sb[SCAN_CHUNK];   // inclusive scan of bsums
    __shared__ int wsum[8];
    __shared__ int wsum2[8];
    const int t = threadIdx.x;
    const int b = blockIdx.x;
    const int lane = t & 31, wid = t >> 5;

    // --- inclusive shuffle scan of the bsums (196 values) ---
    int vb = (t < nblocks) ? __ldg(bsum + t) : 0;
    int sv = vb;
    #pragma unroll
    for (int off = 1; off < 32; off <<= 1) {
        int u = __shfl_up_sync(0xFFFFFFFFu, sv, off);
        if (lane >= off) sv += u;
    }
    if (lane == 31) wsum[wid] = sv;
    __syncthreads();
    if (t < 8) {
        int w = wsum[t];
        #pragma unroll
        for (int off = 1; off < 8; off <<= 1) {
            int u = __shfl_up_sync(0xFFu, w, off);
            if (t >= off) w += u;
        }
        wsum[t] = w;
    }
    __syncthreads();
    sb[t] = sv + ((wid > 0) ? wsum[wid - 1] : 0);
    __syncthreads();
    int bpref = (b > 0) ? sb[b - 1] : 0;

    // --- block-local shuffle scan of padded counts ---
    int i = b * SCAN_CHUNK + t;
    int c  = (i < n) ? __ldg(counts + i) : 0;
    int cp = (c + 3) & ~3;
    int v = cp;
    #pragma unroll
    for (int off = 1; off < 32; off <<= 1) {
        int u = __shfl_up_sync(0xFFFFFFFFu, v, off);
        if (lane >= off) v += u;
    }
    if (lane == 31) wsum2[wid] = v;
    __syncthreads();
    if (t < 8) {
        int w = wsum2[t];
        #pragma unroll
        for (int off = 1; off < 8; off <<= 1) {
            int u = __shfl_up_sync(0xFFu, w, off);
            if (t >= off) w += u;
        }
        wsum2[t] = w;
    }
    __syncthreads();
    int excl = v - cp + ((wid > 0) ? wsum2[wid - 1] : 0);

    int run = bpref + excl;                 // exclusive offset (multiple of 4)
    if (i < n) {
        offsets[i] = run;
        for (int j = c; j < cp; j++) edges[run + j] = 0u;   // pad edges
    }
    if (b == 0 && t == 0) offsets[n] = sb[nblocks - 1];
}

// ---------------------------------------------------------------------------
// 4) permute edges — no atomics, 2 edges/thread (MLP=2, grid still ~977 blocks)
// ---------------------------------------------------------------------------
__global__ void permute_kernel(const int* __restrict__ row,
                               const int* __restrict__ col,
                               const float* __restrict__ val,
                               const int* __restrict__ rank,
                               const int* __restrict__ offsets,
                               unsigned int* __restrict__ edges, int n_edges) {
    int base = (blockIdx.x * blockDim.x + threadIdx.x) * 2;
    if (base + 2 <= n_edges) {
        int2   r = __ldg((const int2*)  (row  + base));
        int2   c = __ldg((const int2*)  (col  + base));
        int2   k = __ldg((const int2*)  (rank + base));
        float2 v = __ldg((const float2*)(val  + base));
        int o0 = __ldg(offsets + r.x);
        int o1 = __ldg(offsets + r.y);
        unsigned short h0 = __half_as_ushort(__float2half_rn(v.x));
        unsigned short h1 = __half_as_ushort(__float2half_rn(v.y));
        edges[o0 + k.x] = (unsigned int)c.x | ((unsigned int)h0 << 16);
        edges[o1 + k.y] = (unsigned int)c.y | ((unsigned int)h1 << 16);
    } else {
        for (int e = base; e < n_edges; e++) {
            int r = __ldg(row + e);
            int pos = __ldg(offsets + r) + __ldg(rank + e);
            unsigned short hv = __half_as_ushort(__float2half_rn(__ldg(val + e)));
            edges[pos] = (unsigned int)__ldg(col + e) | ((unsigned int)hv << 16);
        }
    }
}

// ---------------------------------------------------------------------------
// 5) layer 1 (R11-exact): learn1h = fp16( spmm_h(fea_h) + bias0 );
//    warp/row; uint4 edge descs (4 edges/LDG); fp16 gathers; fp32 accumulate.
//    Also restores counts==0 invariant for the next call.
// ---------------------------------------------------------------------------
__global__ void __launch_bounds__(256)
spmm1_kernel(const uint2* __restrict__ xh,
             uint2* __restrict__ yh,
             const int* __restrict__ offsets,
             const uint4* __restrict__ edges4,
             const float4* __restrict__ bias4,
             int* __restrict__ counts,
             int n_nodes) {
    int gtid = blockIdx.x * blockDim.x + threadIdx.x;
    if (gtid < n_nodes) counts[gtid] = 0;      // restore invariant
    int r = gtid >> 5;
    if (r >= n_nodes) return;
    int lane = threadIdx.x & 31;

    float4 acc = __ldg(bias4 + lane);
    int beg = __ldg(offsets + r);        // multiple of 4
    int end = __ldg(offsets + r + 1);    // multiple of 4

    int i = beg;
    for (; i + 8 <= end; i += 8) {
        uint4 d0 = __ldg(edges4 + (i >> 2));
        uint4 d1 = __ldg(edges4 + (i >> 2) + 1);
        uint2 g0 = __ldg(xh + (size_t)edge_col(d0.x) * 32 + lane);
        uint2 g1 = __ldg(xh + (size_t)edge_col(d0.y) * 32 + lane);
        uint2 g2 = __ldg(xh + (size_t)edge_col(d0.z) * 32 + lane);
        uint2 g3 = __ldg(xh + (size_t)edge_col(d0.w) * 32 + lane);
        uint2 g4 = __ldg(xh + (size_t)edge_col(d1.x) * 32 + lane);
        uint2 g5 = __ldg(xh + (size_t)edge_col(d1.y) * 32 + lane);
        uint2 g6 = __ldg(xh + (size_t)edge_col(d1.z) * 32 + lane);
        uint2 g7 = __ldg(xh + (size_t)edge_col(d1.w) * 32 + lane);
        fma4h(acc, edge_val(d0.x), g0);
        fma4h(acc, edge_val(d0.y), g1);
        fma4h(acc, edge_val(d0.z), g2);
        fma4h(acc, edge_val(d0.w), g3);
        fma4h(acc, edge_val(d1.x), g4);
        fma4h(acc, edge_val(d1.y), g5);
        fma4h(acc, edge_val(d1.z), g6);
        fma4h(acc, edge_val(d1.w), g7);
    }
    if (i < end) {                        // tail of exactly 4 edges
        uint4 d0 = __ldg(edges4 + (i >> 2));
        uint2 g0 = __ldg(xh + (size_t)edge_col(d0.x) * 32 + lane);
        uint2 g1 = __ldg(xh + (size_t)edge_col(d0.y) * 32 + lane);
        uint2 g2 = __ldg(xh + (size_t)edge_col(d0.z) * 32 + lane);
        uint2 g3 = __ldg(xh + (size_t)edge_col(d0.w) * 32 + lane);
        fma4h(acc, edge_val(d0.x), g0);
        fma4h(acc, edge_val(d0.y), g1);
        fma4h(acc, edge_val(d0.z), g2);
        fma4h(acc, edge_val(d0.w), g3);
    }

    yh[(size_t)r * 32 + lane] = pack4h(acc);
}

// ---------------------------------------------------------------------------
// 6) layer 2 + fused final (R11-exact)
// ---------------------------------------------------------------------------
__global__ void __launch_bounds__(256)
spmm2_kernel(const uint2* __restrict__ xh,       // learn1 fp16
             const uint2* __restrict__ feah,     // fea fp16
             float4* __restrict__ out,
             const int* __restrict__ offsets,
             const uint4* __restrict__ edges4,
             const float4* __restrict__ bias4,
             int n_nodes) {
    int gtid = blockIdx.x * blockDim.x + threadIdx.x;
    int r = gtid >> 5;
    if (r >= n_nodes) return;
    int lane = threadIdx.x & 31;

    float4 acc = __ldg(bias4 + lane);
    int beg = __ldg(offsets + r);
    int end = __ldg(offsets + r + 1);

    int i = beg;
    for (; i + 8 <= end; i += 8) {
        uint4 d0 = __ldg(edges4 + (i >> 2));
        uint4 d1 = __ldg(edges4 + (i >> 2) + 1);
        uint2 g0 = __ldg(xh + (size_t)edge_col(d0.x) * 32 + lane);
        uint2 g1 = __ldg(xh + (size_t)edge_col(d0.y) * 32 + lane);
        uint2 g2 = __ldg(xh + (size_t)edge_col(d0.z) * 32 + lane);
        uint2 g3 = __ldg(xh + (size_t)edge_col(d0.w) * 32 + lane);
        uint2 g4 = __ldg(xh + (size_t)edge_col(d1.x) * 32 + lane);
        uint2 g5 = __ldg(xh + (size_t)edge_col(d1.y) * 32 + lane);
        uint2 g6 = __ldg(xh + (size_t)edge_col(d1.z) * 32 + lane);
        uint2 g7 = __ldg(xh + (size_t)edge_col(d1.w) * 32 + lane);
        fma4h(acc, edge_val(d0.x), g0);
        fma4h(acc, edge_val(d0.y), g1);
        fma4h(acc, edge_val(d0.z), g2);
        fma4h(acc, edge_val(d0.w), g3);
        fma4h(acc, edge_val(d1.x), g4);
        fma4h(acc, edge_val(d1.y), g5);
        fma4h(acc, edge_val(d1.z), g6);
        fma4h(acc, edge_val(d1.w), g7);
    }
    if (i < end) {                        // tail of exactly 4 edges
        uint4 d0 = __ldg(edges4 + (i >> 2));
        uint2 g0 = __ldg(xh + (size_t)edge_col(d0.x) * 32 + lane);
        uint2 g1 = __ldg(xh + (size_t)edge_col(d0.y) * 32 + lane);
        uint2 g2 = __ldg(xh + (size_t)edge_col(d0.z) * 32 + lane);
        uint2 g3 = __ldg(xh + (size_t)edge_col(d0.w) * 32 + lane);
        fma4h(acc, edge_val(d0.x), g0);
        fma4h(acc, edge_val(d0.y), g1);
        fma4h(acc, edge_val(d0.z), g2);
        fma4h(acc, edge_val(d0.w), g3);
    }

    size_t idx = (size_t)r * 32 + lane;
    const float inv3 = 1.0f / 3.0f;
    float4 f  = unpack4h(__ldg(feah + idx));   // fp16 residual fea
    float4 l1 = unpack4h(__ldg(xh + idx));     // fp16 residual learn1
    acc.x = (f.x + l1.x + acc.x) * inv3;
    acc.y = (f.y + l1.y + acc.y) * inv3;
    acc.z = (f.z + l1.z + acc.z) * inv3;
    acc.w = (f.w + l1.w + acc.w) * inv3;
    __stcs(out + idx, acc);                    // streaming store
}

extern "C" void kernel_launch(void* const* d_in, const int* in_sizes, int n_in,
                              void* d_out, int out_size) {
    const float* fea     = (const float*)d_in[0];
    const int*   adj_row = (const int*)  d_in[1];
    const int*   adj_col = (const int*)  d_in[2];
    const float* adj_val = (const float*)d_in[3];
    const float* bias    = (const float*)d_in[4];

    int n_edges = in_sizes[1];
    int n_nodes = in_sizes[0] / HIDDEN;
    int total4  = n_nodes * 32;
    int nblocks_scan = (n_nodes + SCAN_CHUNK - 1) / SCAN_CHUNK;   // 196

    uint2* feah;    cudaGetSymbolAddress((void**)&feah,    g_feah);
    uint2* learn1h; cudaGetSymbolAddress((void**)&learn1h, g_learn1h);
    int*   counts;  cudaGetSymbolAddress((void**)&counts,  g_counts);
    int*   offs;    cudaGetSymbolAddress((void**)&offs,    g_offsets);
    int*   rank;    cudaGetSymbolAddress((void**)&rank,    g_rank);
    int*   bsum;    cudaGetSymbolAddress((void**)&bsum,    g_bsum);
    unsigned int* edges; cudaGetSymbolAddress((void**)&edges, g_edges);
    float* out = (float*)d_out;

    const int TPB = 256;

    // 1) fused fp16 convert + histogram/rank
    {
        int work = max(total4, n_edges);
        convert_hist_kernel<<<(work + TPB - 1) / TPB, TPB>>>(
            (const float4*)fea, feah, adj_row, counts, rank, n_edges, total4);
    }

    // 2) block sums of padded counts (shfl reduction)
    scan_bsum_kernel<<<nblocks_scan, SCAN_CHUNK>>>(counts, bsum, n_nodes);

    // 3) offsets scan + pad-edge writes (shfl scans)
    scan_offsets_pad_kernel<<<nblocks_scan, SCAN_CHUNK>>>(counts, bsum, offs,
                                                          edges, n_nodes,
                                                          nblocks_scan);

    // 4) permute edges (2 edges/thread)
    {
        int threads = (n_edges + 1) / 2;
        permute_kernel<<<(threads + TPB - 1) / TPB, TPB>>>(
            adj_row, adj_col, adj_val, rank, offs, edges, n_edges);
    }

    // 5) layer 1 (+ restore counts==0)
    {
        int blocks = (n_nodes * 32 + 255) / 256;
        spmm1_kernel<<<blocks, 256>>>(feah, learn1h, offs, (const uint4*)edges,
                                      (const float4*)bias, counts, n_nodes);
    }

    // 6) layer 2 + fused final
    {
        int blocks = (n_nodes * 32 + 255) / 256;
        spmm2_kernel<<<blocks, 256>>>(learn1h, feah, (float4*)out,
                                      offs, (const uint4*)edges,
                                      (const float4*)(bias + HIDDEN), n_nodes);
    }
}